// round 13
// baseline (speedup 1.0000x reference)
#include <cuda_runtime.h>
#include <cuda_bf16.h>
#include <mma.h>
#include <math.h>
#include <stdint.h>

using namespace nvcuda;

#define HH 512
#define BB 64
#define SS 400
#define VV 50000
#define VS 50400
#define SPL 8
#define SPLW 2
#define SPART 4

// ---------------- scratch ----------------
__device__ __align__(16) float g_gip[SPL * 1536 * 64];
__device__ __align__(16) float g_ghp[SPL * 1536 * 64];
__device__ __align__(16) float g_x2p[SPLW * 512 * 64];
__device__ __align__(16) float g_h[BB * HH];
__device__ __align__(16) float g_spart[SPART * SS * BB];
__device__ __align__(16) float g_attn[SS * BB];
__device__ __align__(16) float g_gs[BB * 2 * HH];
__device__ __align__(16) float g_p[BB];
__device__ __align__(16) float g_wht[512 * 512];     // Wh tf32-rounded, [k][n]
__device__ __align__(16) float g_enct[25600 * 512];  // enc tf32-rounded, [m][k]

__device__ __forceinline__ void cpa16(uint32_t dst, const void* src) {
    asm volatile("cp.async.cg.shared.global [%0], [%1], 16;" :: "r"(dst), "l"(src) : "memory");
}
__device__ __forceinline__ void cpa_commit() {
    asm volatile("cp.async.commit_group;" ::: "memory");
}
template <int N> __device__ __forceinline__ void cpa_wait() {
    asm volatile("cp.async.wait_group %0;" :: "n"(N) : "memory");
}

// =============== score GEMM: wmma tf32 single-pass, cp.async, 2 blk/SM ====
// C = enc[25600,512] @ Wh[512,512]; block tile M=128, N=128, Kchunk=32.
// Warps 4(m) x 2(n); warp tile 32m x 64n; k=8 per mma.
// Epilogue: spart[by*25600+m] = sum_n tanh(C + x2 + b_attn) * v[n].
#define S2_A 0            // 128 rows x 144 B (ld 36 f32)
#define S2_B 18432        // 32 k-rows x 528 B (ld 132 f32)
#define S2_BUF 35328
#define S2_SMEM (2 * S2_BUF)

__global__ void __launch_bounds__(256, 2)
score_tf32(const float* __restrict__ enct, const float* __restrict__ wht,
           const float* __restrict__ x2p, const float* __restrict__ v,
           const float* __restrict__ battn, float* __restrict__ outp)
{
    extern __shared__ __align__(128) char sm[];
    const uint32_t sb = (uint32_t)__cvta_generic_to_shared(sm);
    const int tid = threadIdx.x, wid = tid >> 5;
    const int wm = wid & 3, wn = wid >> 2;
    const int mBase = blockIdx.x * 128, nBase = blockIdx.y * 128;

    wmma::fragment<wmma::accumulator, 16, 16, 8, float> acc[2][4];
    #pragma unroll
    for (int i = 0; i < 2; i++)
        #pragma unroll
        for (int j = 0; j < 4; j++) wmma::fill_fragment(acc[i][j], 0.f);

    auto prefetch = [&](int t) {
        const int k0 = t * 32;
        const uint32_t buf = sb + (t & 1) * S2_BUF;
        // A: 128 rows x 32 f32 (8 x 16B chunks per row) = 1024 chunks
        #pragma unroll
        for (int i = 0; i < 4; i++) {
            int q = tid + 256 * i, r = q >> 3, u = q & 7;
            cpa16(buf + S2_A + r * 144 + u * 16,
                  enct + (size_t)(mBase + r) * 512 + k0 + u * 4);
        }
        // B: 32 k-rows x 128 f32 (32 x 16B chunks per row) = 1024 chunks
        #pragma unroll
        for (int i = 0; i < 4; i++) {
            int q = tid + 256 * i, kk = q >> 5, u = q & 31;
            cpa16(buf + S2_B + kk * 528 + u * 16,
                  wht + (size_t)(k0 + kk) * 512 + nBase + u * 4);
        }
        cpa_commit();
    };

    prefetch(0);
    const int T = 16;            // 512 / 32
    for (int t = 0; t < T; t++) {
        if (t + 1 < T) { prefetch(t + 1); cpa_wait<1>(); }
        else cpa_wait<0>();
        __syncthreads();
        const char* cb = sm + (t & 1) * S2_BUF;
        const float* Af = (const float*)(cb + S2_A);
        const float* Bf = (const float*)(cb + S2_B);
        #pragma unroll
        for (int ks = 0; ks < 4; ks++) {
            wmma::fragment<wmma::matrix_a, 16, 16, 8, wmma::precision::tf32, wmma::row_major> a[2];
            #pragma unroll
            for (int i = 0; i < 2; i++)
                wmma::load_matrix_sync(a[i], Af + (wm * 32 + i * 16) * 36 + ks * 8, 36);
            #pragma unroll
            for (int j = 0; j < 4; j++) {
                wmma::fragment<wmma::matrix_b, 16, 16, 8, wmma::precision::tf32, wmma::row_major> b;
                wmma::load_matrix_sync(b, Bf + ks * 8 * 132 + wn * 64 + j * 16, 132);
                #pragma unroll
                for (int i = 0; i < 2; i++)
                    wmma::mma_sync(acc[i][j], a[i], b, acc[i][j]);
            }
        }
        __syncthreads();
    }

    // epilogue: Cf[128][132] f32 overlay on dead buffers (67584 <= 70656)
    float* Cf = (float*)sm;
    #pragma unroll
    for (int i = 0; i < 2; i++)
        #pragma unroll
        for (int j = 0; j < 4; j++)
            wmma::store_matrix_sync(Cf + (wm * 32 + i * 16) * 132 + wn * 64 + j * 16,
                                    acc[i][j], 132, wmma::mem_row_major);
    __syncthreads();

    const int m = tid >> 1, half = tid & 1, bcol = m & 63;
    const int n0 = half * 64;
    float s = 0.f;
    #pragma unroll 8
    for (int n = n0; n < n0 + 64; n++) {
        int nn = nBase + n;
        float x2v = x2p[nn * 64 + bcol] + x2p[32768 + nn * 64 + bcol] + battn[nn];
        s += tanhf(Cf[m * 132 + n] + x2v) * v[nn];
    }
    s += __shfl_xor_sync(0xffffffffu, s, 1);
    if (!half) outp[(size_t)blockIdx.y * (SS * BB) + mBase + m] = s;
}

// =============== vocab GEMM: wmma tf32 single-pass (R12, passing) =========
#define V2_A 0            // 128 rows x 144 B (ld 36 f32)
#define V2_B 18432        // 64 rows x 144 B
#define V2_BUF 27648
#define V2_SMEM (2 * V2_BUF)

__global__ void __launch_bounds__(256)
vocab_tf32(const float* __restrict__ outW, const float* __restrict__ gs,
           const float* __restrict__ outb, const float* __restrict__ ep,
           float* __restrict__ out)
{
    extern __shared__ __align__(128) char sm[];
    const int tid = threadIdx.x, wid = tid >> 5;
    const int wm = wid & 3, wn = wid >> 2;
    const int mBase = blockIdx.x * 128;

    wmma::fragment<wmma::accumulator, 16, 16, 8, float> acc[2][2];
    #pragma unroll
    for (int i = 0; i < 2; i++)
        #pragma unroll
        for (int j = 0; j < 2; j++) wmma::fill_fragment(acc[i][j], 0.f);

    float4 pa[4], pb[2];
    auto loadG = [&](int k0) {
        #pragma unroll
        for (int i = 0; i < 4; i++) {
            int q = tid + 256 * i, r = q >> 3, c4 = q & 7;
            int mg = mBase + r;
            pa[i] = (mg < VV) ? *(const float4*)(outW + (size_t)mg * 1024 + k0 + c4 * 4)
                              : make_float4(0.f, 0.f, 0.f, 0.f);
        }
        #pragma unroll
        for (int i = 0; i < 2; i++) {
            int q = tid + 256 * i, n = q >> 3, u = q & 7;
            pb[i] = *(const float4*)(gs + (size_t)n * 1024 + k0 + u * 4);
        }
    };
    auto storeT = [&](char* buf) {
        #pragma unroll
        for (int i = 0; i < 4; i++) {
            int q = tid + 256 * i, r = q >> 3, c4 = q & 7;
            float4 w;
            w.x = wmma::__float_to_tf32(pa[i].x);
            w.y = wmma::__float_to_tf32(pa[i].y);
            w.z = wmma::__float_to_tf32(pa[i].z);
            w.w = wmma::__float_to_tf32(pa[i].w);
            *(float4*)(buf + V2_A + r * 144 + c4 * 16) = w;
        }
        #pragma unroll
        for (int i = 0; i < 2; i++) {
            int q = tid + 256 * i, n = q >> 3, u = q & 7;
            float4 w;
            w.x = wmma::__float_to_tf32(pb[i].x);
            w.y = wmma::__float_to_tf32(pb[i].y);
            w.z = wmma::__float_to_tf32(pb[i].z);
            w.w = wmma::__float_to_tf32(pb[i].w);
            *(float4*)(buf + V2_B + n * 144 + u * 16) = w;
        }
    };

    loadG(0);
    storeT(sm);
    __syncthreads();

    const int T = 32;            // 1024 / 32
    for (int t = 0; t < T; t++) {
        char* cb = sm + (t & 1) * V2_BUF;
        if (t + 1 < T) loadG((t + 1) * 32);
        const float* Af = (const float*)(cb + V2_A);
        const float* Bf = (const float*)(cb + V2_B);
        #pragma unroll
        for (int ks = 0; ks < 4; ks++) {
            wmma::fragment<wmma::matrix_a, 16, 16, 8, wmma::precision::tf32, wmma::row_major> a[2];
            #pragma unroll
            for (int i = 0; i < 2; i++)
                wmma::load_matrix_sync(a[i], Af + (wm * 32 + i * 16) * 36 + ks * 8, 36);
            #pragma unroll
            for (int j = 0; j < 2; j++) {
                wmma::fragment<wmma::matrix_b, 16, 16, 8, wmma::precision::tf32, wmma::col_major> b;
                wmma::load_matrix_sync(b, Bf + (wn * 32 + j * 16) * 36 + ks * 8, 36);
                #pragma unroll
                for (int i = 0; i < 2; i++)
                    wmma::mma_sync(acc[i][j], a[i], b, acc[i][j]);
            }
        }
        if (t + 1 < T) storeT(sm + ((t + 1) & 1) * V2_BUF);
        __syncthreads();
    }

    float* Cf = (float*)sm;
    float* ps = (float*)(sm + 33792);
    #pragma unroll
    for (int i = 0; i < 2; i++)
        #pragma unroll
        for (int j = 0; j < 2; j++)
            wmma::store_matrix_sync(Cf + (size_t)(wn * 32 + j * 16) * 132 + wm * 32 + i * 16,
                                    acc[i][j], 132, wmma::mem_col_major);
    if (tid < 64) ps[tid] = ep[tid];
    __syncthreads();

    if (tid < 128) {
        int mg = mBase + tid;
        if (mg < VV) {
            const float SC = 1.0507009873554805f, AL2 = 1.6732632423543772f;
            float ob = outb[mg];
            #pragma unroll 4
            for (int n = 0; n < 64; n++) {
                float vv2 = Cf[n * 132 + tid] + ob;
                vv2 = SC * (vv2 > 0.f ? vv2 : AL2 * expm1f(vv2));
                out[(size_t)n * VS + mg] = vv2 * ps[n];
            }
        }
    }
}

// ============ small split-K GEMM ============
template <bool TRANSA>
__device__ __forceinline__ void small_body(const float* __restrict__ A,
                                           const float* __restrict__ B,
                                           float* __restrict__ outp, int M, int kch)
{
    __shared__ float sA[1024], sB[1024];
    const int tid = threadIdx.x;
    const int tmq = tid & 15, tnq = tid >> 4;
    const int mBase = blockIdx.x * 64;
    const int kBase = blockIdx.y * kch;
    float acc[4][4] = {};

    for (int k0 = kBase; k0 < kBase + kch; k0 += 16) {
        __syncthreads();
        if (!TRANSA) {
            int r = tid >> 2, c4 = tid & 3;
            float4 va = *(const float4*)(A + (size_t)(mBase + r) * 512 + k0 + c4 * 4);
            sA[(c4 * 4 + 0) * 64 + r] = va.x;
            sA[(c4 * 4 + 1) * 64 + r] = va.y;
            sA[(c4 * 4 + 2) * 64 + r] = va.z;
            sA[(c4 * 4 + 3) * 64 + r] = va.w;
        } else {
            #pragma unroll
            for (int j = 0; j < 4; j++) {
                int idx = tid + 256 * j;
                int kk = idx >> 6, m = idx & 63;
                sA[kk * 64 + m] = A[(size_t)(k0 + kk) * 512 + mBase + m];
            }
        }
        {
            int r = tid >> 2, c4 = tid & 3;
            float4 vb = *(const float4*)(B + (size_t)r * 512 + k0 + c4 * 4);
            sB[(c4 * 4 + 0) * 64 + r] = vb.x;
            sB[(c4 * 4 + 1) * 64 + r] = vb.y;
            sB[(c4 * 4 + 2) * 64 + r] = vb.z;
            sB[(c4 * 4 + 3) * 64 + r] = vb.w;
        }
        __syncthreads();
        #pragma unroll
        for (int kk = 0; kk < 16; kk++) {
            float4 a = *(const float4*)&sA[kk * 64 + tmq * 4];
            float4 b = *(const float4*)&sB[kk * 64 + tnq * 4];
            float av[4] = {a.x, a.y, a.z, a.w};
            float bv[4] = {b.x, b.y, b.z, b.w};
            #pragma unroll
            for (int i = 0; i < 4; i++)
                #pragma unroll
                for (int j = 0; j < 4; j++) acc[i][j] += av[i] * bv[j];
        }
    }
    float* dst = outp + (size_t)blockIdx.y * M * 64;
    #pragma unroll
    for (int i = 0; i < 4; i++)
        #pragma unroll
        for (int j = 0; j < 4; j++)
            dst[(size_t)(mBase + tmq * 4 + i) * 64 + tnq * 4 + j] = acc[i][j];
}

template <bool TRANSA>
__global__ void __launch_bounds__(256)
small_gemm(const float* __restrict__ A, const float* __restrict__ B,
           float* __restrict__ outp, int M, int kch)
{
    small_body<TRANSA>(A, B, outp, M, kch);
}

// z=0: W_ih gemm, z=1: W_hh gemm, z=2: Wh -> tf32, z=3: enc -> tf32
__global__ void __launch_bounds__(256)
prologue_fused(const float* __restrict__ A0, const float* __restrict__ B0,
               float* __restrict__ O0,
               const float* __restrict__ A1, const float* __restrict__ B1,
               float* __restrict__ O1, int M,
               const float* __restrict__ Wh, float* __restrict__ wht,
               const float* __restrict__ enc, float* __restrict__ enct)
{
    if (blockIdx.z == 0) { small_body<false>(A0, B0, O0, M, 64); return; }
    if (blockIdx.z == 1) { small_body<false>(A1, B1, O1, M, 64); return; }
    int bid = blockIdx.y * 24 + blockIdx.x;   // 0..191
    if (blockIdx.z == 2) {
        const float4* w4 = (const float4*)Wh;
        float4* d4 = (float4*)wht;
        for (int idx = bid * 256 + threadIdx.x; idx < 512 * 512 / 4; idx += 192 * 256) {
            float4 w = w4[idx];
            w.x = wmma::__float_to_tf32(w.x);
            w.y = wmma::__float_to_tf32(w.y);
            w.z = wmma::__float_to_tf32(w.z);
            w.w = wmma::__float_to_tf32(w.w);
            d4[idx] = w;
        }
        return;
    }
    const float4* e4 = (const float4*)enc;
    float4* d4 = (float4*)enct;
    for (int idx = bid * 256 + threadIdx.x; idx < 25600 * 512 / 4; idx += 192 * 256) {
        float4 w = e4[idx];
        w.x = wmma::__float_to_tf32(w.x);
        w.y = wmma::__float_to_tf32(w.y);
        w.z = wmma::__float_to_tf32(w.z);
        w.w = wmma::__float_to_tf32(w.w);
        d4[idx] = w;
    }
}

// ============ GRU gates ============
__global__ void gru_gates(const float* __restrict__ gip, const float* __restrict__ ghp,
                          const float* __restrict__ b_ih, const float* __restrict__ b_hh,
                          const float* __restrict__ h0,
                          float* __restrict__ gh, float* __restrict__ gs,
                          float* __restrict__ dhid)
{
    int idx = blockIdx.x * 256 + threadIdx.x;
    int b = idx & 63, j = idx >> 6;
    float ir = b_ih[j], iz = b_ih[512 + j], in_ = b_ih[1024 + j];
    float hr = b_hh[j], hz = b_hh[512 + j], hn = b_hh[1024 + j];
    #pragma unroll
    for (int s = 0; s < SPL; s++) {
        const float* gi = gip + s * 98304;
        const float* gq = ghp + s * 98304;
        ir += gi[j * 64 + b];  iz += gi[(512 + j) * 64 + b];  in_ += gi[(1024 + j) * 64 + b];
        hr += gq[j * 64 + b];  hz += gq[(512 + j) * 64 + b];  hn += gq[(1024 + j) * 64 + b];
    }
    float r = 1.f / (1.f + expf(-(ir + hr)));
    float z = 1.f / (1.f + expf(-(iz + hz)));
    float n = tanhf(in_ + r * hn);
    float h = (1.f - z) * n + z * h0[b * 512 + j];
    gh[b * 512 + j] = h;
    gs[b * 1024 + j] = h;
    dhid[b * 512 + j] = h;
}

__global__ void softmax_col(const float* __restrict__ sp, float* __restrict__ attn,
                            float* __restrict__ dattn)
{
    int b = blockIdx.x, tid = threadIdx.x;
    __shared__ float sv[SS];
    __shared__ float rb[8];
    __shared__ float smax, ssum;
    float mx = -3.4e38f;
    for (int s = tid; s < SS; s += 256) {
        float xv = 0.f;
        #pragma unroll
        for (int q = 0; q < SPART; q++) xv += sp[q * (SS * BB) + s * BB + b];
        sv[s] = xv;
        mx = fmaxf(mx, xv);
    }
    #pragma unroll
    for (int o = 16; o; o >>= 1) mx = fmaxf(mx, __shfl_xor_sync(0xffffffffu, mx, o));
    if ((tid & 31) == 0) rb[tid >> 5] = mx;
    __syncthreads();
    if (tid == 0) {
        float m2 = rb[0];
        #pragma unroll
        for (int i = 1; i < 8; i++) m2 = fmaxf(m2, rb[i]);
        smax = m2;
    }
    __syncthreads();
    float sum = 0.f;
    for (int s = tid; s < SS; s += 256) {
        float e = expf(sv[s] - smax);
        sv[s] = e;
        sum += e;
    }
    #pragma unroll
    for (int o = 16; o; o >>= 1) sum += __shfl_xor_sync(0xffffffffu, sum, o);
    if ((tid & 31) == 0) rb[tid >> 5] = sum;
    __syncthreads();
    if (tid == 0) {
        float t = 0.f;
        #pragma unroll
        for (int i = 0; i < 8; i++) t += rb[i];
        ssum = t;
    }
    __syncthreads();
    float inv = 1.f / ssum;
    for (int s = tid; s < SS; s += 256) {
        float a = sv[s] * inv;
        attn[s * BB + b] = a;
        dattn[s * BB + b] = a;
    }
}

__global__ void context_k(const float* __restrict__ attn, const float* __restrict__ enc,
                          float* __restrict__ gs)
{
    int b = blockIdx.x;
    int h = blockIdx.y * 128 + threadIdx.x;
    __shared__ float at[SS];
    for (int s = threadIdx.x; s < SS; s += 128) at[s] = attn[s * BB + b];
    __syncthreads();
    float acc = 0.f;
    const float* p = enc + (size_t)b * 512 + h;
    #pragma unroll 8
    for (int s = 0; s < SS; s++) acc += at[s] * p[(size_t)s * (BB * HH)];
    gs[b * 1024 + 512 + h] = acc;
}

__global__ void pgen_k(const float* __restrict__ gs, const float* __restrict__ x,
                       const float* __restrict__ pWh, const float* __restrict__ pWs,
                       const float* __restrict__ pWx, const float* __restrict__ pWx_b,
                       float* __restrict__ gp, float* __restrict__ dp)
{
    int b = blockIdx.x, tid = threadIdx.x;
    __shared__ float rb[4];
    float a = 0.f;
    for (int j = tid; j < 512; j += 128) {
        a += gs[b * 1024 + 512 + j] * pWh[j]
           + gs[b * 1024 + j] * pWs[j]
           + x[b * 512 + j] * pWx[j];
    }
    #pragma unroll
    for (int o = 16; o; o >>= 1) a += __shfl_xor_sync(0xffffffffu, a, o);
    if ((tid & 31) == 0) rb[tid >> 5] = a;
    __syncthreads();
    if (tid == 0) {
        float t = rb[0] + rb[1] + rb[2] + rb[3];
        float p = 1.f / (1.f + expf(-(t + pWx_b[0])));
        gp[b] = p; dp[b] = p;
    }
}

__global__ void oov_k(const float* __restrict__ attn, const int* __restrict__ mask,
                      const float* __restrict__ gp, float* __restrict__ dout)
{
    int idx = blockIdx.x * 256 + threadIdx.x;
    if (idx >= SS * BB) return;
    int s = idx >> 6, b = idx & 63;
    dout[(size_t)b * VS + VV + s] = (1.f - gp[b]) * attn[idx] * (float)mask[idx];
}

extern "C" void kernel_launch(void* const* d_in, const int* in_sizes, int n_in,
                              void* d_out, int out_size)
{
    const float* x      = (const float*)d_in[0];
    const float* enc    = (const float*)d_in[1];
    const int*   mask   = (const int*)d_in[2];
    const float* h0     = (const float*)d_in[3];
    const float* W_ih   = (const float*)d_in[4];
    const float* W_hh   = (const float*)d_in[5];
    const float* b_ih   = (const float*)d_in[6];
    const float* b_hh   = (const float*)d_in[7];
    const float* out_W  = (const float*)d_in[8];
    const float* out_b  = (const float*)d_in[9];
    const float* v      = (const float*)d_in[10];
    const float* Wh     = (const float*)d_in[11];
    const float* Ws     = (const float*)d_in[12];
    const float* b_attn = (const float*)d_in[13];
    const float* pWh    = (const float*)d_in[14];
    const float* pWs    = (const float*)d_in[15];
    const float* pWx    = (const float*)d_in[16];
    const float* pWx_b  = (const float*)d_in[17];
    float* out = (float*)d_out;

    float *gip, *ghp, *x2p, *hb, *spart, *attn, *gs, *pb, *wht, *enct;
    cudaGetSymbolAddress((void**)&gip,   g_gip);
    cudaGetSymbolAddress((void**)&ghp,   g_ghp);
    cudaGetSymbolAddress((void**)&x2p,   g_x2p);
    cudaGetSymbolAddress((void**)&hb,    g_h);
    cudaGetSymbolAddress((void**)&spart, g_spart);
    cudaGetSymbolAddress((void**)&attn,  g_attn);
    cudaGetSymbolAddress((void**)&gs,    g_gs);
    cudaGetSymbolAddress((void**)&pb,    g_p);
    cudaGetSymbolAddress((void**)&wht,   g_wht);
    cudaGetSymbolAddress((void**)&enct,  g_enct);

    float* dout  = out;
    float* dhid  = out + (size_t)BB * VS;
    float* dp    = dhid + (size_t)BB * HH;
    float* dattn = dp + BB;

    cudaFuncSetAttribute(score_tf32, cudaFuncAttributeMaxDynamicSharedMemorySize, S2_SMEM);
    cudaFuncSetAttribute(vocab_tf32, cudaFuncAttributeMaxDynamicSharedMemorySize, V2_SMEM);

    prologue_fused<<<dim3(24, SPL, 4), 256>>>(W_ih, x, gip, W_hh, h0, ghp, 1536,
                                              Wh, wht, enc, enct);               // 0
    gru_gates<<<128, 256>>>(gip, ghp, b_ih, b_hh, h0, hb, gs, dhid);             // 1
    small_gemm<true><<<dim3(8, SPLW), 256>>>(Ws, hb, x2p, 512, 512 / SPLW);      // 2
    score_tf32<<<dim3(200, SPART), 256, S2_SMEM>>>(enct, wht, x2p, v,            // 3
                                                   b_attn, spart);
    softmax_col<<<64, 256>>>(spart, attn, dattn);                                // 4
    context_k<<<dim3(64, 4), 128>>>(attn, enc, gs);                              // 5
    pgen_k<<<64, 128>>>(gs, x, pWh, pWs, pWx, pWx_b, pb, dp);                    // 6
    vocab_tf32<<<391, 256, V2_SMEM>>>(out_W, gs, out_b, pb, dout);               // 7
    oov_k<<<100, 256>>>(attn, mask, pb, dout);                                   // 8
}

// round 14
// speedup vs baseline: 1.1239x; 1.1239x over previous
#include <cuda_runtime.h>
#include <cuda_bf16.h>
#include <mma.h>
#include <math.h>
#include <stdint.h>

using namespace nvcuda;

#define HH 512
#define BB 64
#define SS 400
#define VV 50000
#define VS 50400
#define SPL 8
#define SPLW 2
#define SPART 8

// ---------------- scratch ----------------
__device__ __align__(16) float g_gip[SPL * 1536 * 64];
__device__ __align__(16) float g_ghp[SPL * 1536 * 64];
__device__ __align__(16) float g_x2p[SPLW * 512 * 64];
__device__ __align__(16) float g_h[BB * HH];
__device__ __align__(16) float g_spart[SPART * SS * BB];
__device__ __align__(16) float g_attn[SS * BB];
__device__ __align__(16) float g_gs[BB * 2 * HH];
__device__ __align__(16) float g_p[BB];
__device__ __align__(16) __nv_bfloat16 g_whh[512 * 512];     // Wh hi, [k][n]
__device__ __align__(16) __nv_bfloat16 g_whl[512 * 512];     // Wh lo, [k][n]
__device__ __align__(16) __nv_bfloat16 g_ench[25600 * 512];  // enc hi, [m][k]
__device__ __align__(16) __nv_bfloat16 g_encl[25600 * 512];  // enc lo, [m][k]

// fast hi/lo bf16 split of two floats
__device__ __forceinline__ void fsplit2(float a0, float a1, uint32_t& hi, uint32_t& lo) {
    uint32_t h;
    asm("cvt.rn.satfinite.bf16x2.f32 %0, %1, %2;" : "=r"(h) : "f"(a1), "f"(a0));
    float h0 = __uint_as_float(h << 16);
    float h1 = __uint_as_float(h & 0xFFFF0000u);
    uint32_t l;
    float r0 = a0 - h0, r1 = a1 - h1;
    asm("cvt.rn.satfinite.bf16x2.f32 %0, %1, %2;" : "=r"(l) : "f"(r1), "f"(r0));
    hi = h; lo = l;
}

__device__ __forceinline__ void cpa16(uint32_t dst, const void* src) {
    asm volatile("cp.async.cg.shared.global [%0], [%1], 16;" :: "r"(dst), "l"(src) : "memory");
}
__device__ __forceinline__ void cpa_commit() {
    asm volatile("cp.async.commit_group;" ::: "memory");
}
template <int N> __device__ __forceinline__ void cpa_wait() {
    asm volatile("cp.async.wait_group %0;" :: "n"(N) : "memory");
}

// =============== score GEMM: wmma bf16 3-term, cp.async, 3 blocks/SM ======
// Block tile M=128, N=64, Kchunk=32; warps 4(m) x 2(n); warp tile 32m x 32n.
// Epilogue: spart[by*25600+m] = sum_n tanh(C + x2 + b_attn) * v[n].
#define S_AH 0          // 128 rows x 96 B (ld 48 bf16)
#define S_AL 12288
#define S_BH 24576      // 32 k-rows x 144 B (ld 72 bf16)
#define S_BL 29184
#define S_BUF 33792
#define S_SMEM (2 * S_BUF)

__global__ void __launch_bounds__(256, 3)
score_wmma(const __nv_bfloat16* __restrict__ ench, const __nv_bfloat16* __restrict__ encl,
           const __nv_bfloat16* __restrict__ whh, const __nv_bfloat16* __restrict__ whl,
           const float* __restrict__ x2p, const float* __restrict__ v,
           const float* __restrict__ battn, float* __restrict__ outp)
{
    extern __shared__ __align__(128) char sm[];
    const uint32_t sb = (uint32_t)__cvta_generic_to_shared(sm);
    const int tid = threadIdx.x, wid = tid >> 5;
    const int wm = wid & 3, wn = wid >> 2;
    const int mBase = blockIdx.x * 128, nBase = blockIdx.y * 64;

    wmma::fragment<wmma::accumulator, 16, 16, 16, float> acc[2][2];
    #pragma unroll
    for (int i = 0; i < 2; i++)
        #pragma unroll
        for (int j = 0; j < 2; j++) wmma::fill_fragment(acc[i][j], 0.f);

    auto prefetch = [&](int t) {
        const int k0 = t * 32;
        const uint32_t buf = sb + (t & 1) * S_BUF;
        // A: 128 rows x 32 bf16 (4 x 16B per row) per plane = 512 chunks/plane
        #pragma unroll
        for (int i = 0; i < 2; i++) {
            int q = tid + 256 * i, r = q >> 2, u = q & 3;
            size_t goff = (size_t)(mBase + r) * 512 + k0 + u * 8;
            cpa16(buf + S_AH + r * 96 + u * 16, ench + goff);
            cpa16(buf + S_AL + r * 96 + u * 16, encl + goff);
        }
        // B: 32 k-rows x 64 bf16 (8 x 16B per row) per plane = 256 chunks/plane
        {
            int kk = tid >> 3, u = tid & 7;
            size_t goff = (size_t)(k0 + kk) * 512 + nBase + u * 8;
            cpa16(buf + S_BH + kk * 144 + u * 16, whh + goff);
            cpa16(buf + S_BL + kk * 144 + u * 16, whl + goff);
        }
        cpa_commit();
    };

    prefetch(0);
    const int T = 16;            // 512 / 32
    for (int t = 0; t < T; t++) {
        if (t + 1 < T) { prefetch(t + 1); cpa_wait<1>(); }
        else cpa_wait<0>();
        __syncthreads();
        const char* cb = sm + (t & 1) * S_BUF;
        const __nv_bfloat16* Ah = (const __nv_bfloat16*)(cb + S_AH);
        const __nv_bfloat16* Al = (const __nv_bfloat16*)(cb + S_AL);
        const __nv_bfloat16* Bh = (const __nv_bfloat16*)(cb + S_BH);
        const __nv_bfloat16* Bl = (const __nv_bfloat16*)(cb + S_BL);
        #pragma unroll
        for (int ks = 0; ks < 2; ks++) {
            wmma::fragment<wmma::matrix_a, 16, 16, 16, __nv_bfloat16, wmma::row_major> ah[2], al[2];
            #pragma unroll
            for (int i = 0; i < 2; i++) {
                wmma::load_matrix_sync(ah[i], Ah + (wm * 32 + i * 16) * 48 + ks * 16, 48);
                wmma::load_matrix_sync(al[i], Al + (wm * 32 + i * 16) * 48 + ks * 16, 48);
            }
            #pragma unroll
            for (int j = 0; j < 2; j++) {
                wmma::fragment<wmma::matrix_b, 16, 16, 16, __nv_bfloat16, wmma::row_major> bh, bl;
                wmma::load_matrix_sync(bh, Bh + ks * 16 * 72 + wn * 32 + j * 16, 72);
                wmma::load_matrix_sync(bl, Bl + ks * 16 * 72 + wn * 32 + j * 16, 72);
                #pragma unroll
                for (int i = 0; i < 2; i++) {
                    wmma::mma_sync(acc[i][j], ah[i], bh, acc[i][j]);
                    wmma::mma_sync(acc[i][j], ah[i], bl, acc[i][j]);
                    wmma::mma_sync(acc[i][j], al[i], bh, acc[i][j]);
                }
            }
        }
        __syncthreads();
    }

    // epilogue: Cf[128][68] f32 overlay on dead buffers (34816 <= 67584)
    float* Cf = (float*)sm;
    #pragma unroll
    for (int i = 0; i < 2; i++)
        #pragma unroll
        for (int j = 0; j < 2; j++)
            wmma::store_matrix_sync(Cf + (wm * 32 + i * 16) * 68 + wn * 32 + j * 16,
                                    acc[i][j], 68, wmma::mem_row_major);
    __syncthreads();

    const int m = tid >> 1, half = tid & 1, bcol = m & 63;
    const int n0 = half * 32;
    float s = 0.f;
    #pragma unroll 8
    for (int n = n0; n < n0 + 32; n++) {
        int nn = nBase + n;
        float x2v = x2p[nn * 64 + bcol] + x2p[32768 + nn * 64 + bcol] + battn[nn];
        s += tanhf(Cf[m * 68 + n] + x2v) * v[nn];
    }
    s += __shfl_xor_sync(0xffffffffu, s, 1);
    if (!half) outp[(size_t)blockIdx.y * (SS * BB) + mBase + m] = s;
}

// =============== vocab GEMM: wmma tf32 single-pass (R12, passing) =========
#define V2_A 0            // 128 rows x 144 B (ld 36 f32)
#define V2_B 18432        // 64 rows x 144 B
#define V2_BUF 27648
#define V2_SMEM (2 * V2_BUF)

__global__ void __launch_bounds__(256)
vocab_tf32(const float* __restrict__ outW, const float* __restrict__ gs,
           const float* __restrict__ outb, const float* __restrict__ ep,
           float* __restrict__ out)
{
    extern __shared__ __align__(128) char sm[];
    const int tid = threadIdx.x, wid = tid >> 5;
    const int wm = wid & 3, wn = wid >> 2;
    const int mBase = blockIdx.x * 128;

    wmma::fragment<wmma::accumulator, 16, 16, 8, float> acc[2][2];
    #pragma unroll
    for (int i = 0; i < 2; i++)
        #pragma unroll
        for (int j = 0; j < 2; j++) wmma::fill_fragment(acc[i][j], 0.f);

    float4 pa[4], pb[2];
    auto loadG = [&](int k0) {
        #pragma unroll
        for (int i = 0; i < 4; i++) {
            int q = tid + 256 * i, r = q >> 3, c4 = q & 7;
            int mg = mBase + r;
            pa[i] = (mg < VV) ? *(const float4*)(outW + (size_t)mg * 1024 + k0 + c4 * 4)
                              : make_float4(0.f, 0.f, 0.f, 0.f);
        }
        #pragma unroll
        for (int i = 0; i < 2; i++) {
            int q = tid + 256 * i, n = q >> 3, u = q & 7;
            pb[i] = *(const float4*)(gs + (size_t)n * 1024 + k0 + u * 4);
        }
    };
    auto storeT = [&](char* buf) {
        #pragma unroll
        for (int i = 0; i < 4; i++) {
            int q = tid + 256 * i, r = q >> 3, c4 = q & 7;
            float4 w;
            w.x = wmma::__float_to_tf32(pa[i].x);
            w.y = wmma::__float_to_tf32(pa[i].y);
            w.z = wmma::__float_to_tf32(pa[i].z);
            w.w = wmma::__float_to_tf32(pa[i].w);
            *(float4*)(buf + V2_A + r * 144 + c4 * 16) = w;
        }
        #pragma unroll
        for (int i = 0; i < 2; i++) {
            int q = tid + 256 * i, n = q >> 3, u = q & 7;
            float4 w;
            w.x = wmma::__float_to_tf32(pb[i].x);
            w.y = wmma::__float_to_tf32(pb[i].y);
            w.z = wmma::__float_to_tf32(pb[i].z);
            w.w = wmma::__float_to_tf32(pb[i].w);
            *(float4*)(buf + V2_B + n * 144 + u * 16) = w;
        }
    };

    loadG(0);
    storeT(sm);
    __syncthreads();

    const int T = 32;            // 1024 / 32
    for (int t = 0; t < T; t++) {
        char* cb = sm + (t & 1) * V2_BUF;
        if (t + 1 < T) loadG((t + 1) * 32);
        const float* Af = (const float*)(cb + V2_A);
        const float* Bf = (const float*)(cb + V2_B);
        #pragma unroll
        for (int ks = 0; ks < 4; ks++) {
            wmma::fragment<wmma::matrix_a, 16, 16, 8, wmma::precision::tf32, wmma::row_major> a[2];
            #pragma unroll
            for (int i = 0; i < 2; i++)
                wmma::load_matrix_sync(a[i], Af + (wm * 32 + i * 16) * 36 + ks * 8, 36);
            #pragma unroll
            for (int j = 0; j < 2; j++) {
                wmma::fragment<wmma::matrix_b, 16, 16, 8, wmma::precision::tf32, wmma::col_major> b;
                wmma::load_matrix_sync(b, Bf + (wn * 32 + j * 16) * 36 + ks * 8, 36);
                #pragma unroll
                for (int i = 0; i < 2; i++)
                    wmma::mma_sync(acc[i][j], a[i], b, acc[i][j]);
            }
        }
        if (t + 1 < T) storeT(sm + ((t + 1) & 1) * V2_BUF);
        __syncthreads();
    }

    float* Cf = (float*)sm;
    float* ps = (float*)(sm + 33792);
    #pragma unroll
    for (int i = 0; i < 2; i++)
        #pragma unroll
        for (int j = 0; j < 2; j++)
            wmma::store_matrix_sync(Cf + (size_t)(wn * 32 + j * 16) * 132 + wm * 32 + i * 16,
                                    acc[i][j], 132, wmma::mem_col_major);
    if (tid < 64) ps[tid] = ep[tid];
    __syncthreads();

    if (tid < 128) {
        int mg = mBase + tid;
        if (mg < VV) {
            const float SC = 1.0507009873554805f, AL2 = 1.6732632423543772f;
            float ob = outb[mg];
            #pragma unroll 4
            for (int n = 0; n < 64; n++) {
                float vv2 = Cf[n * 132 + tid] + ob;
                vv2 = SC * (vv2 > 0.f ? vv2 : AL2 * expm1f(vv2));
                out[(size_t)n * VS + mg] = vv2 * ps[n];
            }
        }
    }
}

// ============ small split-K GEMM ============
template <bool TRANSA>
__device__ __forceinline__ void small_body(const float* __restrict__ A,
                                           const float* __restrict__ B,
                                           float* __restrict__ outp, int M, int kch)
{
    __shared__ float sA[1024], sB[1024];
    const int tid = threadIdx.x;
    const int tmq = tid & 15, tnq = tid >> 4;
    const int mBase = blockIdx.x * 64;
    const int kBase = blockIdx.y * kch;
    float acc[4][4] = {};

    for (int k0 = kBase; k0 < kBase + kch; k0 += 16) {
        __syncthreads();
        if (!TRANSA) {
            int r = tid >> 2, c4 = tid & 3;
            float4 va = *(const float4*)(A + (size_t)(mBase + r) * 512 + k0 + c4 * 4);
            sA[(c4 * 4 + 0) * 64 + r] = va.x;
            sA[(c4 * 4 + 1) * 64 + r] = va.y;
            sA[(c4 * 4 + 2) * 64 + r] = va.z;
            sA[(c4 * 4 + 3) * 64 + r] = va.w;
        } else {
            #pragma unroll
            for (int j = 0; j < 4; j++) {
                int idx = tid + 256 * j;
                int kk = idx >> 6, m = idx & 63;
                sA[kk * 64 + m] = A[(size_t)(k0 + kk) * 512 + mBase + m];
            }
        }
        {
            int r = tid >> 2, c4 = tid & 3;
            float4 vb = *(const float4*)(B + (size_t)r * 512 + k0 + c4 * 4);
            sB[(c4 * 4 + 0) * 64 + r] = vb.x;
            sB[(c4 * 4 + 1) * 64 + r] = vb.y;
            sB[(c4 * 4 + 2) * 64 + r] = vb.z;
            sB[(c4 * 4 + 3) * 64 + r] = vb.w;
        }
        __syncthreads();
        #pragma unroll
        for (int kk = 0; kk < 16; kk++) {
            float4 a = *(const float4*)&sA[kk * 64 + tmq * 4];
            float4 b = *(const float4*)&sB[kk * 64 + tnq * 4];
            float av[4] = {a.x, a.y, a.z, a.w};
            float bv[4] = {b.x, b.y, b.z, b.w};
            #pragma unroll
            for (int i = 0; i < 4; i++)
                #pragma unroll
                for (int j = 0; j < 4; j++) acc[i][j] += av[i] * bv[j];
        }
    }
    float* dst = outp + (size_t)blockIdx.y * M * 64;
    #pragma unroll
    for (int i = 0; i < 4; i++)
        #pragma unroll
        for (int j = 0; j < 4; j++)
            dst[(size_t)(mBase + tmq * 4 + i) * 64 + tnq * 4 + j] = acc[i][j];
}

template <bool TRANSA>
__global__ void __launch_bounds__(256)
small_gemm(const float* __restrict__ A, const float* __restrict__ B,
           float* __restrict__ outp, int M, int kch)
{
    small_body<TRANSA>(A, B, outp, M, kch);
}

// z=0: W_ih gemm, z=1: W_hh gemm, z=2: Wh -> bf16 hi/lo, z=3: enc -> bf16 hi/lo
__global__ void __launch_bounds__(256)
prologue_fused(const float* __restrict__ A0, const float* __restrict__ B0,
               float* __restrict__ O0,
               const float* __restrict__ A1, const float* __restrict__ B1,
               float* __restrict__ O1, int M,
               const float* __restrict__ Wh,
               __nv_bfloat16* __restrict__ whh, __nv_bfloat16* __restrict__ whl,
               const float* __restrict__ enc,
               __nv_bfloat16* __restrict__ ench, __nv_bfloat16* __restrict__ encl)
{
    if (blockIdx.z == 0) { small_body<false>(A0, B0, O0, M, 64); return; }
    if (blockIdx.z == 1) { small_body<false>(A1, B1, O1, M, 64); return; }
    int bid = blockIdx.y * 24 + blockIdx.x;   // 0..191
    if (blockIdx.z == 2) {
        const float2* w2 = (const float2*)Wh;
        for (int idx = bid * 256 + threadIdx.x; idx < 512 * 512 / 2; idx += 192 * 256) {
            float2 w = w2[idx];
            uint32_t h, l;
            fsplit2(w.x, w.y, h, l);
            *(uint32_t*)(whh + (size_t)idx * 2) = h;
            *(uint32_t*)(whl + (size_t)idx * 2) = l;
        }
        return;
    }
    const float4* e4 = (const float4*)enc;
    for (int idx = bid * 256 + threadIdx.x; idx < 25600 * 512 / 4; idx += 192 * 256) {
        float4 w = e4[idx];
        uint32_t h0, l0, h1, l1;
        fsplit2(w.x, w.y, h0, l0);
        fsplit2(w.z, w.w, h1, l1);
        *(uint2*)(ench + (size_t)idx * 4) = make_uint2(h0, h1);
        *(uint2*)(encl + (size_t)idx * 4) = make_uint2(l0, l1);
    }
}

// ============ GRU gates ============
__global__ void gru_gates(const float* __restrict__ gip, const float* __restrict__ ghp,
                          const float* __restrict__ b_ih, const float* __restrict__ b_hh,
                          const float* __restrict__ h0,
                          float* __restrict__ gh, float* __restrict__ gs,
                          float* __restrict__ dhid)
{
    int idx = blockIdx.x * 256 + threadIdx.x;
    int b = idx & 63, j = idx >> 6;
    float ir = b_ih[j], iz = b_ih[512 + j], in_ = b_ih[1024 + j];
    float hr = b_hh[j], hz = b_hh[512 + j], hn = b_hh[1024 + j];
    #pragma unroll
    for (int s = 0; s < SPL; s++) {
        const float* gi = gip + s * 98304;
        const float* gq = ghp + s * 98304;
        ir += gi[j * 64 + b];  iz += gi[(512 + j) * 64 + b];  in_ += gi[(1024 + j) * 64 + b];
        hr += gq[j * 64 + b];  hz += gq[(512 + j) * 64 + b];  hn += gq[(1024 + j) * 64 + b];
    }
    float r = 1.f / (1.f + expf(-(ir + hr)));
    float z = 1.f / (1.f + expf(-(iz + hz)));
    float n = tanhf(in_ + r * hn);
    float h = (1.f - z) * n + z * h0[b * 512 + j];
    gh[b * 512 + j] = h;
    gs[b * 1024 + j] = h;
    dhid[b * 512 + j] = h;
}

__global__ void softmax_col(const float* __restrict__ sp, float* __restrict__ attn,
                            float* __restrict__ dattn)
{
    int b = blockIdx.x, tid = threadIdx.x;
    __shared__ float sv[SS];
    __shared__ float rb[8];
    __shared__ float smax, ssum;
    float mx = -3.4e38f;
    for (int s = tid; s < SS; s += 256) {
        float xv = 0.f;
        #pragma unroll
        for (int q = 0; q < SPART; q++) xv += sp[q * (SS * BB) + s * BB + b];
        sv[s] = xv;
        mx = fmaxf(mx, xv);
    }
    #pragma unroll
    for (int o = 16; o; o >>= 1) mx = fmaxf(mx, __shfl_xor_sync(0xffffffffu, mx, o));
    if ((tid & 31) == 0) rb[tid >> 5] = mx;
    __syncthreads();
    if (tid == 0) {
        float m2 = rb[0];
        #pragma unroll
        for (int i = 1; i < 8; i++) m2 = fmaxf(m2, rb[i]);
        smax = m2;
    }
    __syncthreads();
    float sum = 0.f;
    for (int s = tid; s < SS; s += 256) {
        float e = expf(sv[s] - smax);
        sv[s] = e;
        sum += e;
    }
    #pragma unroll
    for (int o = 16; o; o >>= 1) sum += __shfl_xor_sync(0xffffffffu, sum, o);
    if ((tid & 31) == 0) rb[tid >> 5] = sum;
    __syncthreads();
    if (tid == 0) {
        float t = 0.f;
        #pragma unroll
        for (int i = 0; i < 8; i++) t += rb[i];
        ssum = t;
    }
    __syncthreads();
    float inv = 1.f / ssum;
    for (int s = tid; s < SS; s += 256) {
        float a = sv[s] * inv;
        attn[s * BB + b] = a;
        dattn[s * BB + b] = a;
    }
}

__global__ void context_k(const float* __restrict__ attn, const float* __restrict__ enc,
                          float* __restrict__ gs)
{
    int b = blockIdx.x;
    int h = blockIdx.y * 128 + threadIdx.x;
    __shared__ float at[SS];
    for (int s = threadIdx.x; s < SS; s += 128) at[s] = attn[s * BB + b];
    __syncthreads();
    float acc = 0.f;
    const float* p = enc + (size_t)b * 512 + h;
    #pragma unroll 8
    for (int s = 0; s < SS; s++) acc += at[s] * p[(size_t)s * (BB * HH)];
    gs[b * 1024 + 512 + h] = acc;
}

__global__ void pgen_k(const float* __restrict__ gs, const float* __restrict__ x,
                       const float* __restrict__ pWh, const float* __restrict__ pWs,
                       const float* __restrict__ pWx, const float* __restrict__ pWx_b,
                       float* __restrict__ gp, float* __restrict__ dp)
{
    int b = blockIdx.x, tid = threadIdx.x;
    __shared__ float rb[4];
    float a = 0.f;
    for (int j = tid; j < 512; j += 128) {
        a += gs[b * 1024 + 512 + j] * pWh[j]
           + gs[b * 1024 + j] * pWs[j]
           + x[b * 512 + j] * pWx[j];
    }
    #pragma unroll
    for (int o = 16; o; o >>= 1) a += __shfl_xor_sync(0xffffffffu, a, o);
    if ((tid & 31) == 0) rb[tid >> 5] = a;
    __syncthreads();
    if (tid == 0) {
        float t = rb[0] + rb[1] + rb[2] + rb[3];
        float p = 1.f / (1.f + expf(-(t + pWx_b[0])));
        gp[b] = p; dp[b] = p;
    }
}

__global__ void oov_k(const float* __restrict__ attn, const int* __restrict__ mask,
                      const float* __restrict__ gp, float* __restrict__ dout)
{
    int idx = blockIdx.x * 256 + threadIdx.x;
    if (idx >= SS * BB) return;
    int s = idx >> 6, b = idx & 63;
    dout[(size_t)b * VS + VV + s] = (1.f - gp[b]) * attn[idx] * (float)mask[idx];
}

extern "C" void kernel_launch(void* const* d_in, const int* in_sizes, int n_in,
                              void* d_out, int out_size)
{
    const float* x      = (const float*)d_in[0];
    const float* enc    = (const float*)d_in[1];
    const int*   mask   = (const int*)d_in[2];
    const float* h0     = (const float*)d_in[3];
    const float* W_ih   = (const float*)d_in[4];
    const float* W_hh   = (const float*)d_in[5];
    const float* b_ih   = (const float*)d_in[6];
    const float* b_hh   = (const float*)d_in[7];
    const float* out_W  = (const float*)d_in[8];
    const float* out_b  = (const float*)d_in[9];
    const float* v      = (const float*)d_in[10];
    const float* Wh     = (const float*)d_in[11];
    const float* Ws     = (const float*)d_in[12];
    const float* b_attn = (const float*)d_in[13];
    const float* pWh    = (const float*)d_in[14];
    const float* pWs    = (const float*)d_in[15];
    const float* pWx    = (const float*)d_in[16];
    const float* pWx_b  = (const float*)d_in[17];
    float* out = (float*)d_out;

    float *gip, *ghp, *x2p, *hb, *spart, *attn, *gs, *pb;
    __nv_bfloat16 *whh, *whl, *ench, *encl;
    cudaGetSymbolAddress((void**)&gip,   g_gip);
    cudaGetSymbolAddress((void**)&ghp,   g_ghp);
    cudaGetSymbolAddress((void**)&x2p,   g_x2p);
    cudaGetSymbolAddress((void**)&hb,    g_h);
    cudaGetSymbolAddress((void**)&spart, g_spart);
    cudaGetSymbolAddress((void**)&attn,  g_attn);
    cudaGetSymbolAddress((void**)&gs,    g_gs);
    cudaGetSymbolAddress((void**)&pb,    g_p);
    cudaGetSymbolAddress((void**)&whh,   g_whh);
    cudaGetSymbolAddress((void**)&whl,   g_whl);
    cudaGetSymbolAddress((void**)&ench,  g_ench);
    cudaGetSymbolAddress((void**)&encl,  g_encl);

    float* dout  = out;
    float* dhid  = out + (size_t)BB * VS;
    float* dp    = dhid + (size_t)BB * HH;
    float* dattn = dp + BB;

    cudaFuncSetAttribute(score_wmma, cudaFuncAttributeMaxDynamicSharedMemorySize, S_SMEM);
    cudaFuncSetAttribute(vocab_tf32, cudaFuncAttributeMaxDynamicSharedMemorySize, V2_SMEM);

    prologue_fused<<<dim3(24, SPL, 4), 256>>>(W_ih, x, gip, W_hh, h0, ghp, 1536,
                                              Wh, whh, whl, enc, ench, encl);    // 0
    gru_gates<<<128, 256>>>(gip, ghp, b_ih, b_hh, h0, hb, gs, dhid);             // 1
    small_gemm<true><<<dim3(8, SPLW), 256>>>(Ws, hb, x2p, 512, 512 / SPLW);      // 2
    score_wmma<<<dim3(200, SPART), 256, S_SMEM>>>(ench, encl, whh, whl, x2p, v,  // 3
                                                  b_attn, spart);
    softmax_col<<<64, 256>>>(spart, attn, dattn);                                // 4
    context_k<<<dim3(64, 4), 128>>>(attn, enc, gs);                              // 5
    pgen_k<<<64, 128>>>(gs, x, pWh, pWs, pWx, pWx_b, pb, dp);                    // 6
    vocab_tf32<<<391, 256, V2_SMEM>>>(out_W, gs, out_b, pb, dout);               // 7
    oov_k<<<100, 256>>>(attn, mask, pb, dout);                                   // 8
}